// round 1
// baseline (speedup 1.0000x reference)
#include <cuda_runtime.h>

// Problem constants
#define B      16
#define CIN    32
#define COUT   32
#define DD     32      // input D=H=W
#define NQ     512
#define JW     27648   // COUT*CIN*27
#define DOUT   30
#define KPAD   28      // 27 padded to 28 for float4 weight loads

// Scratch for per-sample conv weights, k-dim padded to 28.
// Layout: ((b*COUT + co)*CIN + ci)*KPAD + k ; k==27 slot stays 0 (zero-init,
// never written) so the padded FMA lane is a no-op.
__device__ float g_weights[B * COUT * CIN * KPAD];   // 1.75 MB

// ---------------------------------------------------------------------------
// Kernel 1: weights[b, j] = sum_q query[b,q] * lut[q,j], j in [0, 27648)
// One thread per j, accumulating all 16 batches -> lut read exactly once.
// ---------------------------------------------------------------------------
__global__ __launch_bounds__(256) void weight_gemm_kernel(
    const float* __restrict__ query,   // [B, NQ]
    const float* __restrict__ lut)     // [NQ, JW]
{
    __shared__ float qs[B * NQ];       // 32 KB
    const int tid = threadIdx.x;
    for (int i = tid; i < B * NQ; i += blockDim.x) qs[i] = query[i];
    __syncthreads();

    const int j = blockIdx.x * blockDim.x + tid;   // grid covers exactly JW

    float acc[B];
#pragma unroll
    for (int b = 0; b < B; b++) acc[b] = 0.f;

#pragma unroll 4
    for (int q = 0; q < NQ; q++) {
        const float lv = lut[q * JW + j];
#pragma unroll
        for (int b = 0; b < B; b++)
            acc[b] = fmaf(qs[b * NQ + q], lv, acc[b]);
    }

    const int k    = j % 27;
    const int rest = j / 27;           // co*CIN + ci
#pragma unroll
    for (int b = 0; b < B; b++)
        g_weights[(b * COUT * CIN + rest) * KPAD + k] = acc[b];
}

// ---------------------------------------------------------------------------
// Kernel 2: grouped valid conv3d.
// Block: one (b, d_out, co-half[16]) ; threads (32, 30): x=w (w<30 active), y=h.
// Per ci: stage 3x32x32 input slab + 16x28 weight tile in smem,
// keep 27 input taps in registers, FMA against float4 weight broadcasts.
// ---------------------------------------------------------------------------
__global__ __launch_bounds__(960, 1) void conv_kernel(
    const float* __restrict__ target,  // [B, CIN, 32, 32, 32]
    float* __restrict__ out)           // [B, COUT, 30, 30, 30]
{
    __shared__ __align__(16) float slab[3 * DD * DD];   // 12 KB
    __shared__ __align__(16) float wsm[16][KPAD];       // 1.75 KB

    const int d  = blockIdx.x;          // 0..29
    const int b  = blockIdx.y;          // 0..15
    const int cg = blockIdx.z;          // 0..1 (co half)

    const int w   = threadIdx.x;        // 0..31, active if < 30
    const int h   = threadIdx.y;        // 0..29
    const int tid = threadIdx.y * 32 + threadIdx.x;     // 0..959
    const bool active = (w < DOUT);

    float acc[16];
#pragma unroll
    for (int i = 0; i < 16; i++) acc[i] = 0.f;

    const float* tgt_b = target + (size_t)b * CIN * DD * DD * DD;
    const float* wbase = g_weights + ((size_t)(b * COUT + cg * 16) * CIN) * KPAD;

    for (int ci = 0; ci < CIN; ci++) {
        // ---- stage input slab: rows d..d+2, full 32x32 planes ----
        const float* src = tgt_b + ((size_t)ci * DD + d) * (DD * DD);
#pragma unroll
        for (int i = tid; i < 3 * DD * DD; i += 960)
            slab[i] = src[i];

        // ---- stage 16x28 weight tile for this ci ----
        {
            const float* wsrc = wbase + ci * KPAD;      // co stride = CIN*KPAD
            for (int i = tid; i < 16 * KPAD; i += 960) {
                int co = i / KPAD, k = i % KPAD;
                wsm[co][k] = wsrc[co * (CIN * KPAD) + k];
            }
        }
        __syncthreads();

        if (active) {
            // 27 taps -> registers (28th lane is a zero-pad partner)
            float in[KPAD];
#pragma unroll
            for (int kd = 0; kd < 3; kd++)
#pragma unroll
                for (int kh = 0; kh < 3; kh++)
#pragma unroll
                    for (int kw = 0; kw < 3; kw++)
                        in[kd * 9 + kh * 3 + kw] =
                            slab[(kd * DD + (h + kh)) * DD + (w + kw)];
            in[27] = 0.f;

#pragma unroll
            for (int co = 0; co < 16; co++) {
                const float4* wrow = reinterpret_cast<const float4*>(&wsm[co][0]);
                float a = acc[co];
#pragma unroll
                for (int v = 0; v < 7; v++) {
                    const float4 wv = wrow[v];           // LDS.128 broadcast
                    a = fmaf(in[v * 4 + 0], wv.x, a);
                    a = fmaf(in[v * 4 + 1], wv.y, a);
                    a = fmaf(in[v * 4 + 2], wv.z, a);
                    a = fmaf(in[v * 4 + 3], wv.w, a);
                }
                acc[co] = a;
            }
        }
        __syncthreads();
    }

    if (active) {
        const int cobase = cg * 16;
        float* obase = out + (((size_t)(b * COUT + cobase) * DOUT + d) * (DOUT * DOUT))
                           + h * DOUT + w;
#pragma unroll
        for (int co = 0; co < 16; co++)
            obase[(size_t)co * (DOUT * DOUT * DOUT)] = acc[co];
    }
}

// ---------------------------------------------------------------------------
extern "C" void kernel_launch(void* const* d_in, const int* in_sizes, int n_in,
                              void* d_out, int out_size)
{
    const float* query  = (const float*)d_in[0];   // [16, 512]
    const float* target = (const float*)d_in[1];   // [16, 32, 32, 32, 32]
    const float* lut    = (const float*)d_in[2];   // [512, 27648]
    float* out = (float*)d_out;                    // [16, 32, 30, 30, 30]

    (void)in_sizes; (void)n_in; (void)out_size;

    weight_gemm_kernel<<<JW / 256, 256>>>(query, lut);

    dim3 grid(DOUT, B, 2);
    dim3 block(32, DOUT, 1);
    conv_kernel<<<grid, block>>>(target, out);
}

// round 8
// speedup vs baseline: 1.3575x; 1.3575x over previous
#include <cuda_runtime.h>

// Problem constants
#define B      16
#define CIN    32
#define COUT   32
#define DD     32      // input D=H=W
#define NQ     512
#define JW     27648   // COUT*CIN*27
#define DOUT   30
#define KPAD   28      // 27 padded to 28 (pad weight == 0, never multiplied)

// Per-sample conv weights, k padded to 28. Layout:
//   ((b*COUT + co)*CIN + ci)*KPAD + k   ; k==27 never written -> stays 0.
__device__ float g_weights[B * COUT * CIN * KPAD];   // 1.75 MB, zero-init .bss

// ---------------- packed f32x2 helpers ----------------
__device__ __forceinline__ unsigned long long pack2(float lo, float hi) {
    unsigned long long r;
    asm("mov.b64 %0, {%1, %2};" : "=l"(r) : "f"(lo), "f"(hi));
    return r;
}
__device__ __forceinline__ unsigned long long fma2(unsigned long long a,
                                                   unsigned long long b,
                                                   unsigned long long c) {
    unsigned long long d;
    asm("fma.rn.f32x2 %0, %1, %2, %3;" : "=l"(d) : "l"(a), "l"(b), "l"(c));
    return d;
}
__device__ __forceinline__ void unpack2(unsigned long long v, float& lo, float& hi) {
    asm("mov.b64 {%0, %1}, %2;" : "=f"(lo), "=f"(hi) : "l"(v));
}

// ---------------------------------------------------------------------------
// Kernel 1: weights[b, j] = sum_q query[b,q] * lut[q,j]
// ---------------------------------------------------------------------------
__global__ __launch_bounds__(256) void weight_gemm_kernel(
    const float* __restrict__ query,   // [B, NQ]
    const float* __restrict__ lut)     // [NQ, JW]
{
    __shared__ float qs[B * NQ];       // 32 KB
    const int tid = threadIdx.x;
    for (int i = tid; i < B * NQ; i += blockDim.x) qs[i] = query[i];
    __syncthreads();

    const int j = blockIdx.x * blockDim.x + tid;   // grid covers exactly JW

    float acc[B];
#pragma unroll
    for (int b = 0; b < B; b++) acc[b] = 0.f;

#pragma unroll 4
    for (int q = 0; q < NQ; q++) {
        const float lv = lut[q * JW + j];
#pragma unroll
        for (int b = 0; b < B; b++)
            acc[b] = fmaf(qs[b * NQ + q], lv, acc[b]);
    }

    const int k    = j % 27;
    const int rest = j / 27;           // co*CIN + ci
#pragma unroll
    for (int b = 0; b < B; b++)
        g_weights[(b * COUT * CIN + rest) * KPAD + k] = acc[b];
}

// ---------------------------------------------------------------------------
// Kernel 2: grouped valid conv3d, packed f32x2 FMA over co-pairs.
// Block: (d, b, co-half[16]); threads (32,30). Double-buffered slab+weights,
// ONE __syncthreads per ci.
// Weight smem layout per buffer: float2 wsm[pair(8)][k(28)] with
//   wsm[p][k] = { W[2p][k], W[2p+1][k] }  -> ulonglong2 load covers k,k+1.
// Taps 0..25 processed as 13 (b0,b1) pairs; tap 26 with the j=13 .x half only
// (the .y half is the k=27 zero pad - skipped).
// ---------------------------------------------------------------------------
__global__ __launch_bounds__(960, 1) void conv_kernel(
    const float* __restrict__ target,  // [B, CIN, 32,32,32]
    float* __restrict__ out)           // [B, COUT, 30,30,30]
{
    __shared__ __align__(16) float  slab[2][3 * DD * DD];   // 2 x 12 KB
    __shared__ __align__(16) float2 wsm[2][8][KPAD];        // 2 x 1.75 KB

    const int d  = blockIdx.x;          // 0..29
    const int b  = blockIdx.y;          // 0..15
    const int cg = blockIdx.z;          // 0..1

    const int w   = threadIdx.x;        // 0..31 (active < 30)
    const int h   = threadIdx.y;        // 0..29
    const int tid = h * 32 + w;
    const bool active = (w < DOUT);

    const float* tgt_b = target + (size_t)b * CIN * DD * DD * DD;
    const float* wbase = g_weights + (size_t)(b * COUT + cg * 16) * CIN * KPAD;

    // ---- stage ci = 0 into buffer 0 ----
    {
        const float4* src = (const float4*)(tgt_b + (size_t)d * DD * DD);
        if (tid < 768) ((float4*)slab[0])[tid] = src[tid];
        if (tid < 16 * KPAD) {
            int co = tid / KPAD, k = tid % KPAD;
            ((float*)wsm[0])[((co >> 1) * KPAD + k) * 2 + (co & 1)] =
                wbase[(size_t)co * CIN * KPAD + k];
        }
    }
    __syncthreads();

    unsigned long long acc[8];
#pragma unroll
    for (int p = 0; p < 8; p++) acc[p] = pack2(0.f, 0.f);

    int buf = 0;
    for (int ci = 0; ci < CIN; ci++) {
        // ---- prefetch ci+1 into the other buffer (no sync needed yet) ----
        if (ci + 1 < CIN) {
            const float4* src =
                (const float4*)(tgt_b + ((size_t)(ci + 1) * DD + d) * DD * DD);
            if (tid < 768) ((float4*)slab[buf ^ 1])[tid] = src[tid];
            if (tid < 16 * KPAD) {
                int co = tid / KPAD, k = tid % KPAD;
                ((float*)wsm[buf ^ 1])[((co >> 1) * KPAD + k) * 2 + (co & 1)] =
                    wbase[((size_t)co * CIN + (ci + 1)) * KPAD + k];
            }
        }

        if (active) {
            // 27 taps -> registers
            float in[27];
#pragma unroll
            for (int kd = 0; kd < 3; kd++)
#pragma unroll
                for (int kh = 0; kh < 3; kh++)
#pragma unroll
                    for (int kw = 0; kw < 3; kw++)
                        in[kd * 9 + kh * 3 + kw] =
                            slab[buf][(kd * DD + (h + kh)) * DD + (w + kw)];

            const ulonglong2* wq = (const ulonglong2*)wsm[buf]; // [p*14 + j]
#pragma unroll
            for (int j = 0; j < 13; j++) {
                const unsigned long long b0 = pack2(in[2 * j],     in[2 * j]);
                const unsigned long long b1 = pack2(in[2 * j + 1], in[2 * j + 1]);
#pragma unroll
                for (int p = 0; p < 8; p++) {
                    const ulonglong2 wv = wq[p * 14 + j];   // LDS.128 broadcast
                    acc[p] = fma2(wv.x, b0, acc[p]);
                    acc[p] = fma2(wv.y, b1, acc[p]);
                }
            }
            // tail tap 26 (k=27 pad half skipped)
            {
                const unsigned long long b0 = pack2(in[26], in[26]);
#pragma unroll
                for (int p = 0; p < 8; p++) {
                    const ulonglong2 wv = wq[p * 14 + 13];
                    acc[p] = fma2(wv.x, b0, acc[p]);
                }
            }
        }
        __syncthreads();
        buf ^= 1;
    }

    if (active) {
        float* obase = out + (((size_t)(b * COUT + cg * 16) * DOUT + d) * DOUT * DOUT)
                           + h * DOUT + w;
#pragma unroll
        for (int p = 0; p < 8; p++) {
            float lo, hi;
            unpack2(acc[p], lo, hi);
            obase[(size_t)(2 * p)     * DOUT * DOUT * DOUT] = lo;
            obase[(size_t)(2 * p + 1) * DOUT * DOUT * DOUT] = hi;
        }
    }
}

// ---------------------------------------------------------------------------
extern "C" void kernel_launch(void* const* d_in, const int* in_sizes, int n_in,
                              void* d_out, int out_size)
{
    const float* query  = (const float*)d_in[0];   // [16, 512]
    const float* target = (const float*)d_in[1];   // [16, 32, 32, 32, 32]
    const float* lut    = (const float*)d_in[2];   // [512, 27648]
    float* out = (float*)d_out;                    // [16, 32, 30, 30, 30]

    (void)in_sizes; (void)n_in; (void)out_size;

    weight_gemm_kernel<<<JW / 256, 256>>>(query, lut);

    dim3 grid(DOUT, B, 2);
    dim3 block(32, DOUT, 1);
    conv_kernel<<<grid, block>>>(target, out);
}